// round 15
// baseline (speedup 1.0000x reference)
#include <cuda_runtime.h>
#include <cuda_fp16.h>
#include <math.h>
#include <stdint.h>

// ---------------------------------------------------------------------------
// SinkhornNetwork on GB300 — round 14: fp16-split mma.sync GEMM with
// single-sync software pipeline.
//   C = Ah*Wh + Al*Wh + Ah*Wl (fp32 acc), W pre-scaled x32, epilogue x1/32.
//   Per chunk: STS(i+1) [regs->other buffer, overlaps compute], COMP(i),
//   LDG(i+2) [regs], ONE __syncthreads. Conversion ALU + STS hide behind MMA.
// ---------------------------------------------------------------------------

static constexpr int MROWS = 512 * 36;   // 18432

__device__ float g_vis1[MROWS * 512];
__device__ float g_cat [MROWS * 388];
__device__ float g_h256[MROWS * 256];
__device__ float g_logits[MROWS * 36];

// ---------------- helpers ----------------

__device__ __forceinline__ uint32_t smem_u32(const void* p) {
    uint32_t a;
    asm("{ .reg .u64 t; cvta.to.shared.u64 t, %1; cvt.u32.u64 %0, t; }"
        : "=r"(a) : "l"(p));
    return a;
}

__device__ __forceinline__ void ldm4(uint32_t* d, uint32_t a) {
    asm volatile("ldmatrix.sync.aligned.m8n8.x4.shared.b16 {%0,%1,%2,%3}, [%4];"
        : "=r"(d[0]), "=r"(d[1]), "=r"(d[2]), "=r"(d[3]) : "r"(a));
}

__device__ __forceinline__ void mma16816(float* c, const uint32_t* a, const uint32_t* b) {
    asm volatile(
        "mma.sync.aligned.m16n8k16.row.col.f32.f16.f16.f32 "
        "{%0,%1,%2,%3},{%4,%5,%6,%7},{%8,%9},{%0,%1,%2,%3};"
        : "+f"(c[0]), "+f"(c[1]), "+f"(c[2]), "+f"(c[3])
        : "r"(a[0]), "r"(a[1]), "r"(a[2]), "r"(a[3]), "r"(b[0]), "r"(b[1]));
}

// fp16 split of two floats: hi = packed {lo16=f16(a), hi16=f16(b)},
// lo = packed residuals.
__device__ __forceinline__ void split2h(float a, float b, uint32_t& hi, uint32_t& lo) {
    uint32_t h;
    asm("cvt.rn.f16x2.f32 %0, %1, %2;" : "=r"(h) : "f"(b), "f"(a));
    float2 hf = __half22float2(*reinterpret_cast<const __half2*>(&h));
    float ra = a - hf.x;
    float rb = b - hf.y;
    uint32_t l;
    asm("cvt.rn.f16x2.f32 %0, %1, %2;" : "=r"(l) : "f"(rb), "f"(ra));
    hi = h; lo = l;
}

// ---------------- mma.sync GEMM (256 threads, NT=128) ----------------
// C[128 x 128] tile = relu((A*W^T)*1/32 + bias), W pre-scaled x32.
// grid = (N/128, M/128), 256 threads (8 warps, 4(m) x 2(n)), warp tile 32x64.
// smem rows padded to 80B (conflict-free ldmatrix). Two stages.

static constexpr int   ROWB   = 80;
static constexpr int   TILEB  = 128 * ROWB;     // 10240
static constexpr int   STAGEB = 4 * TILEB;      // 40960 (Ahi,Alo,Whi,Wlo)
static constexpr int   SMEMB  = 2 * STAGEB;     // 81920
static constexpr float WSCALE = 32.0f;
static constexpr float WINV   = 1.0f / 32.0f;

#define LDG_BODY(KC, AR, WR) do {                                              \
    const int _k0 = (KC) * 32;                                                 \
    _Pragma("unroll")                                                          \
    for (int _it = 0; _it < 4; _it++) {                                        \
        int _idx = tid + _it * 256;                                            \
        int _row = _idx >> 3;                                                  \
        int _k   = _k0 + ((_idx & 7) << 2);                                    \
        if (_k + 4 <= K) {                                                     \
            AR[_it] = *reinterpret_cast<const float4*>(Ap + (size_t)_row * lda + _k); \
            WR[_it] = *reinterpret_cast<const float4*>(Wp + (size_t)_row * K + _k);   \
        } else {                                                               \
            AR[_it] = make_float4(0.f, 0.f, 0.f, 0.f);                         \
            WR[_it] = make_float4(0.f, 0.f, 0.f, 0.f);                         \
        }                                                                      \
    }                                                                          \
} while (0)

#define STS_BODY(AR, WR, SPTR) do {                                            \
    char* _s = (SPTR);                                                         \
    _Pragma("unroll")                                                          \
    for (int _it = 0; _it < 4; _it++) {                                        \
        int _idx = tid + _it * 256;                                            \
        int _row = _idx >> 3;                                                  \
        int _off = _row * ROWB + (((_idx & 7) << 2) << 1);                     \
        uint32_t _h0, _l0, _h1, _l1;                                           \
        split2h(AR[_it].x, AR[_it].y, _h0, _l0);                               \
        split2h(AR[_it].z, AR[_it].w, _h1, _l1);                               \
        *reinterpret_cast<uint2*>(_s + _off)             = make_uint2(_h0, _h1); \
        *reinterpret_cast<uint2*>(_s + TILEB + _off)     = make_uint2(_l0, _l1); \
        split2h(WR[_it].x * WSCALE, WR[_it].y * WSCALE, _h0, _l0);             \
        split2h(WR[_it].z * WSCALE, WR[_it].w * WSCALE, _h1, _l1);             \
        *reinterpret_cast<uint2*>(_s + 2 * TILEB + _off) = make_uint2(_h0, _h1); \
        *reinterpret_cast<uint2*>(_s + 3 * TILEB + _off) = make_uint2(_l0, _l1); \
    }                                                                          \
} while (0)

__global__ void __launch_bounds__(256, 1) mma_gemm(
    const float* __restrict__ A, int lda,
    const float* __restrict__ W,
    const float* __restrict__ bias,
    float* __restrict__ C, int ldc,
    int K, int nch)
{
    extern __shared__ char sm[];
    const uint32_t sbase = smem_u32(sm);

    const int tid  = threadIdx.x;
    const int lane = tid & 31;
    const int w    = tid >> 5;
    const int wm   = w & 3;        // warp row (x32)
    const int wn   = w >> 2;       // warp col (x64)
    const long bm  = (long)blockIdx.y * 128;
    const long bn  = (long)blockIdx.x * 128;

    const float* Ap = A + bm * (long)lda;
    const float* Wp = W + bn * (long)K;

    float acc[2][8][4];
    #pragma unroll
    for (int mt = 0; mt < 2; mt++)
        #pragma unroll
        for (int nt = 0; nt < 8; nt++)
            #pragma unroll
            for (int q = 0; q < 4; q++)
                acc[mt][nt][q] = 0.0f;

    const int r8 = lane & 7;
    const int g  = lane >> 3;
    auto COMP = [&](int stg) {
        const uint32_t sb = sbase + (uint32_t)stg * STAGEB;
        #pragma unroll
        for (int s = 0; s < 2; s++) {       // two k16 steps per 32-col chunk
            uint32_t ah[2][4], al[2][4];
            #pragma unroll
            for (int mt = 0; mt < 2; mt++) {
                int row = wm * 32 + mt * 16 + ((g & 1) << 3) + r8;
                int co  = (s * 16 + ((g >> 1) << 3)) << 1;
                ldm4(ah[mt], sb + row * ROWB + co);
                ldm4(al[mt], sb + TILEB + row * ROWB + co);
            }
            #pragma unroll
            for (int np = 0; np < 4; np++) {
                int row = wn * 64 + np * 16 + ((g >> 1) << 3) + r8;
                int co  = (s * 16 + ((g & 1) << 3)) << 1;
                uint32_t bh[2][2], bl[2][2], q[4];
                ldm4(q, sb + 2 * TILEB + row * ROWB + co);
                bh[0][0] = q[0]; bh[0][1] = q[1]; bh[1][0] = q[2]; bh[1][1] = q[3];
                ldm4(q, sb + 3 * TILEB + row * ROWB + co);
                bl[0][0] = q[0]; bl[0][1] = q[1]; bl[1][0] = q[2]; bl[1][1] = q[3];
                #pragma unroll
                for (int mt = 0; mt < 2; mt++)
                    #pragma unroll
                    for (int h = 0; h < 2; h++) {
                        mma16816(acc[mt][np * 2 + h], ah[mt], bh[h]);   // hi*hi
                        mma16816(acc[mt][np * 2 + h], al[mt], bh[h]);   // lo*hi
                        mma16816(acc[mt][np * 2 + h], ah[mt], bl[h]);   // hi*lo
                    }
            }
        }
    };

    // --- software pipeline: chunk c lives in smem buffer (c & 1).
    // Iteration i (even): STS chunk i+1 (regs set1 -> buf1), COMP chunk i
    // (buf0), LDG chunk i+2 -> set0, ONE sync. Then the odd mirror.
    float4 ar0[4], wr0[4], ar1[4], wr1[4];

    LDG_BODY(0, ar0, wr0);
    STS_BODY(ar0, wr0, sm);
    if (nch > 1) LDG_BODY(1, ar1, wr1);
    __syncthreads();

    for (int i = 0; i < nch; i += 2) {
        // even chunk i
        if (i + 1 < nch) STS_BODY(ar1, wr1, sm + STAGEB);
        COMP(0);
        if (i + 2 < nch) LDG_BODY(i + 2, ar0, wr0);
        __syncthreads();
        // odd chunk i+1
        if (i + 1 < nch) {
            if (i + 2 < nch) STS_BODY(ar0, wr0, sm);
            COMP(1);
            if (i + 3 < nch) LDG_BODY(i + 3, ar1, wr1);
            __syncthreads();
        }
    }

    // epilogue: *1/32, + bias, relu
    #pragma unroll
    for (int mt = 0; mt < 2; mt++) {
        const long r0 = bm + wm * 32 + mt * 16 + (lane >> 2);
        #pragma unroll
        for (int nt = 0; nt < 8; nt++) {
            const long col = bn + wn * 64 + nt * 8 + (lane & 3) * 2;
            float2 bv = *reinterpret_cast<const float2*>(bias + col);
            float2 o0, o1;
            o0.x = fmaxf(fmaf(acc[mt][nt][0], WINV, bv.x), 0.f);
            o0.y = fmaxf(fmaf(acc[mt][nt][1], WINV, bv.y), 0.f);
            o1.x = fmaxf(fmaf(acc[mt][nt][2], WINV, bv.x), 0.f);
            o1.y = fmaxf(fmaf(acc[mt][nt][3], WINV, bv.y), 0.f);
            *reinterpret_cast<float2*>(C + r0 * (long)ldc + col)       = o0;
            *reinterpret_cast<float2*>(C + (r0 + 8) * (long)ldc + col) = o1;
        }
    }
}

// ---------------- small kernels ----------------

__global__ void pos_relu_kernel(const float* __restrict__ seq, float* __restrict__ cat)
{
    int idx = blockIdx.x * blockDim.x + threadIdx.x;
    if (idx < MROWS * 4) {
        int r = idx >> 2, c = idx & 3;
        float v = seq[(long)r * 3076 + 2560 + c];
        cat[(long)r * 388 + 256 + c] = fmaxf(v, 0.f);
    }
}

__global__ void __launch_bounds__(288) fc_tanh_kernel(
    const float* __restrict__ A,
    const float* __restrict__ W,
    const float* __restrict__ bias,
    float* __restrict__ out)
{
    __shared__ float Ws[36 * 260];
    __shared__ float Asm[8 * 260];
    __shared__ float bs[36];

    const int tid = threadIdx.x;
    const long rowBase = (long)blockIdx.x * 8;

    for (int i = tid; i < 36 * 256; i += 288) {
        int n = i >> 8, k = i & 255;
        Ws[n * 260 + k] = W[i];
    }
    for (int i = tid; i < 8 * 256; i += 288) {
        int r = i >> 8, k = i & 255;
        Asm[r * 260 + k] = A[(rowBase + r) * 256 + k];
    }
    if (tid < 36) bs[tid] = bias[tid];
    __syncthreads();

    const int r = tid / 36;
    const int n = tid % 36;
    if (r < 8) {
        const float* a = &Asm[r * 260];
        const float* wv = &Ws[n * 260];
        float s = bs[n];
        #pragma unroll 8
        for (int k = 0; k < 256; k++)
            s = fmaf(a[k], wv[k], s);
        out[(rowBase + r) * 36 + n] = tanhf(s);
    }
}

__global__ void __launch_bounds__(64) sinkhorn_kernel(
    const float* __restrict__ logits, float* __restrict__ out)
{
    const int b = blockIdx.x;
    const int j = threadIdx.x;
    __shared__ float xm[36][37];
    __shared__ float rowlse[36];
    float col[36];
    const bool act = (j < 36);

    if (act) {
        #pragma unroll
        for (int i = 0; i < 36; i++) {
            float t = logits[((long)b * 36 + i) * 36 + j];
            col[i] = expf(t * 20.0f);
        }
    }

    for (int it = 0; it < 20; it++) {
        if (act) {
            #pragma unroll
            for (int i = 0; i < 36; i++) xm[i][j] = col[i];
        }
        __syncthreads();
        if (act) {
            float m = -INFINITY;
            #pragma unroll
            for (int k = 0; k < 36; k++) m = fmaxf(m, xm[j][k]);
            float s = 0.f;
            #pragma unroll
            for (int k = 0; k < 36; k++) s += expf(xm[j][k] - m);
            rowlse[j] = m + logf(s);
        }
        __syncthreads();
        if (act) {
            #pragma unroll
            for (int i = 0; i < 36; i++) col[i] -= rowlse[i];
            float m = -INFINITY;
            #pragma unroll
            for (int i = 0; i < 36; i++) m = fmaxf(m, col[i]);
            float s = 0.f;
            #pragma unroll
            for (int i = 0; i < 36; i++) s += expf(col[i] - m);
            float l = m + logf(s);
            #pragma unroll
            for (int i = 0; i < 36; i++) col[i] -= l;
        }
        __syncthreads();
    }

    if (act) {
        #pragma unroll
        for (int i = 0; i < 36; i++)
            out[((long)b * 36 + i) * 36 + j] = expf(col[i]);
    }
}

// ---------------- launch ----------------

extern "C" void kernel_launch(void* const* d_in, const int* in_sizes, int n_in,
                              void* d_out, int out_size)
{
    const float* seq      = (const float*)d_in[0];
    const float* W1_txt_w = (const float*)d_in[1];
    const float* W1_txt_b = (const float*)d_in[2];
    const float* W1_vis_w = (const float*)d_in[3];
    const float* W1_vis_b = (const float*)d_in[4];
    const float* W2_vis_w = (const float*)d_in[5];
    const float* W2_vis_b = (const float*)d_in[6];
    const float* W1_sen_w = (const float*)d_in[7];
    const float* W1_sen_b = (const float*)d_in[8];
    const float* Wfcp_w   = (const float*)d_in[9];
    const float* Wfcp_b   = (const float*)d_in[10];
    const float* Wfc_w    = (const float*)d_in[11];
    const float* Wfc_b    = (const float*)d_in[12];
    float* out = (float*)d_out;

    float *p_vis1, *p_cat, *p_h256, *p_logits;
    cudaGetSymbolAddress((void**)&p_vis1,   g_vis1);
    cudaGetSymbolAddress((void**)&p_cat,    g_cat);
    cudaGetSymbolAddress((void**)&p_h256,   g_h256);
    cudaGetSymbolAddress((void**)&p_logits, g_logits);

    cudaFuncSetAttribute(mma_gemm, cudaFuncAttributeMaxDynamicSharedMemorySize, SMEMB);

    const int gy = MROWS / 128;   // 144

    // vis1: [M,2048] -> [M,512]
    mma_gemm<<<dim3(4, gy), 256, SMEMB>>>(
        seq + 512, 3076, W1_vis_w, W1_vis_b, p_vis1, 512, 2048, 64);

    // txt: [M,512] -> cat[:,0:128)
    mma_gemm<<<dim3(1, gy), 256, SMEMB>>>(
        seq + 0, 3076, W1_txt_w, W1_txt_b, p_cat + 0, 388, 512, 16);

    // vis2: [M,512] -> cat[:,128:256)
    mma_gemm<<<dim3(1, gy), 256, SMEMB>>>(
        p_vis1, 512, W2_vis_w, W2_vis_b, p_cat + 128, 388, 512, 16);

    // sen: [M,512] -> cat[:,260:388)
    mma_gemm<<<dim3(1, gy), 256, SMEMB>>>(
        seq + 2564, 3076, W1_sen_w, W1_sen_b, p_cat + 260, 388, 512, 16);

    // pos: relu -> cat[:,256:260)
    pos_relu_kernel<<<(MROWS * 4 + 255) / 256, 256>>>(seq, p_cat);

    // fc_pos: [M,388] -> [M,256]
    mma_gemm<<<dim3(2, gy), 256, SMEMB>>>(
        p_cat, 388, Wfcp_w, Wfcp_b, p_h256, 256, 388, 13);

    // fc: [M,256] -> [M,36], tanh
    fc_tanh_kernel<<<MROWS / 8, 288>>>(p_h256, Wfc_w, Wfc_b, p_logits);

    // sinkhorn
    sinkhorn_kernel<<<512, 64>>>(p_logits, out);
}